// round 13
// baseline (speedup 1.0000x reference)
#include <cuda_runtime.h>
#include <cuda_bf16.h>
#include <cuda_fp16.h>
#include <cstdint>

#define N_NODES 131072
#define N_EDGES 2097152
#define N_GRAPHS 64
#define NODES_PER_GRAPH 2048
#define D_IN 128
#define D_EMB 64
#define D_HID 128
#define N_ACT 2048

// ---------------- scratch (device globals) -----------------------------------
__device__ uint32_t g_zlb [N_NODES * 32];        // zl as packed FP16 pairs, 128B/row
__device__ float4   g_zr4 [N_NODES * D_EMB / 4]; // in @ Wr.T (self term, f32)
__device__ float4   g_h4  [N_NODES * D_EMB / 4]; // h1 (layer-2 h never stored)
__device__ float    g_pool[N_GRAPHS * D_EMB];

__device__ int g_deg [N_NODES];
__device__ int g_off [N_NODES];
__device__ int g_cur [N_NODES];
__device__ int g_csr [N_EDGES];
__device__ int g_total;

// fragment-packed bf16 weights: index ((ks*4 + t)*128 + col)
__device__ uint4 g_w1f[(128 / 16) * 4 * 128];   // 4096 entries, 64 KB
__device__ uint4 g_w2f[(64 / 16) * 4 * 128];    // 2048 entries, 32 KB

#define G_ZR  ((float*)g_zr4)
#define G_H   ((float*)g_h4)

// ---------------- bf16/fp16 helpers --------------------------------------------
__device__ __forceinline__ uint32_t pack_bf16(__nv_bfloat16 a, __nv_bfloat16 b) {
    __nv_bfloat162 p = __halves2bfloat162(a, b);   // a = low half (even dim)
    return *reinterpret_cast<uint32_t*>(&p);
}

__device__ __forceinline__ void split_pair(float v0, float v1,
                                           uint32_t& hi, uint32_t& lo) {
    __nv_bfloat16 h0 = __float2bfloat16_rn(v0);
    __nv_bfloat16 h1 = __float2bfloat16_rn(v1);
    __nv_bfloat16 l0 = __float2bfloat16_rn(v0 - __bfloat162float(h0));
    __nv_bfloat16 l1 = __float2bfloat16_rn(v1 - __bfloat162float(h1));
    hi = pack_bf16(h0, h1);
    lo = pack_bf16(l0, l1);
}

// pack two f32 -> one uint32 of fp16x2 (messages; fp16 eps 4.9e-4, 8x better than bf16)
__device__ __forceinline__ uint32_t pack_half2(float v0, float v1) {
    __half2 p = __float22half2_rn(make_float2(v0, v1));
    return *reinterpret_cast<uint32_t*>(&p);
}

#define MMA_BF16(C, a0, a1, a2, a3, b0, b1)                                   \
    asm volatile(                                                             \
        "mma.sync.aligned.m16n8k16.row.col.f32.bf16.bf16.f32 "                \
        "{%0,%1,%2,%3}, {%4,%5,%6,%7}, {%8,%9}, {%0,%1,%2,%3};"               \
        : "+f"((C)[0]), "+f"((C)[1]), "+f"((C)[2]), "+f"((C)[3])              \
        : "r"(a0), "r"(a1), "r"(a2), "r"(a3), "r"(b0), "r"(b1))

// unpack-accumulate: 1 uint4 = 8 fp16 dims -> 8 f32 accumulators (HW cvt)
__device__ __forceinline__ void acc8(float* a, uint4 u) {
    float2 f0 = __half22float2(*reinterpret_cast<__half2*>(&u.x));
    float2 f1 = __half22float2(*reinterpret_cast<__half2*>(&u.y));
    float2 f2 = __half22float2(*reinterpret_cast<__half2*>(&u.z));
    float2 f3 = __half22float2(*reinterpret_cast<__half2*>(&u.w));
    a[0] += f0.x;  a[1] += f0.y;
    a[2] += f1.x;  a[3] += f1.y;
    a[4] += f2.x;  a[5] += f2.y;
    a[6] += f3.x;  a[7] += f3.y;
}

// ================== weight fragment builder ====================================
template <int K>
__device__ __forceinline__ uint4 make_wfrag(const float* __restrict__ Wrow,
                                            int ks, int t) {
    int p0 = ks * 8 + t;
    int p1 = ks * 8 + t + 4;
    uint4 f;
    uint32_t h0, l0, h1, l1;
    split_pair(Wrow[2 * p0], Wrow[2 * p0 + 1], h0, l0);
    split_pair(Wrow[2 * p1], Wrow[2 * p1 + 1], h1, l1);
    f.x = h0; f.y = h1; f.z = l0; f.w = l1;
    return f;
}

// ================== fused init: zero deg/pool/counter + wsplit =================
__global__ void init_kernel(const float* __restrict__ W1l,
                            const float* __restrict__ W1r,
                            const float* __restrict__ W2l,
                            const float* __restrict__ W2r) {
    int i = blockIdx.x * blockDim.x + threadIdx.x;
    if (i < N_NODES) g_deg[i] = 0;
    if (i < N_GRAPHS * D_EMB) g_pool[i] = 0.f;
    if (i == 0) g_total = 0;
    if (i < 8 * 4 * 128) {
        int col = i & 127, tt = (i >> 7) & 3, ks = i >> 9;
        const float* Wrow = (col < 64) ? (W1l + col * 128) : (W1r + (col - 64) * 128);
        g_w1f[i] = make_wfrag<128>(Wrow, ks, tt);
    }
    if (i < 4 * 4 * 128) {
        int col = i & 127, tt = (i >> 7) & 3, ks = i >> 9;
        const float* Wrow = (col < 64) ? (W2l + col * 64) : (W2r + (col - 64) * 64);
        g_w2f[i] = make_wfrag<64>(Wrow, ks, tt);
    }
}

// ================== CSR: hist -> alloc (warp-agg atomic) -> scatter ============
__global__ void hist_kernel(const int* __restrict__ dst) {
    int stride = gridDim.x * blockDim.x;
    for (int e = blockIdx.x * blockDim.x + threadIdx.x; e < N_EDGES; e += stride)
        atomicAdd(&g_deg[dst[e]], 1);
}

__global__ void alloc_kernel() {
    int i = blockIdx.x * blockDim.x + threadIdx.x;
    int lane = threadIdx.x & 31;
    int d = g_deg[i];
    int p = d;
#pragma unroll
    for (int s = 1; s < 32; s <<= 1) {
        int v = __shfl_up_sync(0xffffffffu, p, s);
        if (lane >= s) p += v;
    }
    int wsum = __shfl_sync(0xffffffffu, p, 31);
    int base = 0;
    if (lane == 31) base = atomicAdd(&g_total, wsum);
    base = __shfl_sync(0xffffffffu, base, 31);
    int off = base + p - d;
    g_off[i] = off;
    g_cur[i] = off;
}

__global__ void scatter_kernel(const int* __restrict__ src,
                               const int* __restrict__ dst) {
    int stride = gridDim.x * blockDim.x;
    for (int e = blockIdx.x * blockDim.x + threadIdx.x; e < N_EDGES; e += stride) {
        int d = dst[e];
        int pos = atomicAdd(&g_cur[d], 1);
        g_csr[pos] = src[e];
    }
}

// ================== tensor-core dual projection (3xBF16, m16n8k16) ============
// zl half written as PACKED FP16 (messages); zr half stays f32.
template <int K>
__global__ void __launch_bounds__(256, 2) lin_tc_kernel(const float* __restrict__ in_param) {
    constexpr int SU = K / 2 + 4;
    extern __shared__ uint32_t sm[];
    uint32_t* Ah = sm;              // [128][SU]
    uint32_t* Al = Ah + 128 * SU;

    const float* in  = (K == D_EMB) ? G_H   : in_param;
    const uint4* Wf  = (K == D_EMB) ? g_w2f : g_w1f;

    const int tid = threadIdx.x;
    const int node0 = blockIdx.x * 128;

    const float4* inv = (const float4*)(in + (size_t)node0 * K);
    for (int idx = tid; idx < 128 * K / 4; idx += 256) {
        float4 v = inv[idx];
        int row = idx / (K / 4), w0 = (idx % (K / 4)) * 2;
        uint32_t h01, l01, h23, l23;
        split_pair(v.x, v.y, h01, l01);
        split_pair(v.z, v.w, h23, l23);
        Ah[row * SU + w0] = h01;  Ah[row * SU + w0 + 1] = h23;
        Al[row * SU + w0] = l01;  Al[row * SU + w0 + 1] = l23;
    }
    __syncthreads();

    const int warp = tid >> 5, lane = tid & 31;
    const int g = lane >> 2, t = lane & 3;
    const int m_base = (warp >> 1) * 32;
    const int cb     = (warp & 1) * 64;

    float c[2][8][4];
#pragma unroll
    for (int mt = 0; mt < 2; mt++)
#pragma unroll
        for (int nt = 0; nt < 8; nt++)
#pragma unroll
            for (int j = 0; j < 4; j++) c[mt][nt][j] = 0.f;

#pragma unroll
    for (int ks = 0; ks < K / 16; ks++) {
        const int kk = ks * 8 + t;
        uint32_t ah[2][4], al[2][4];
#pragma unroll
        for (int mt = 0; mt < 2; mt++) {
            int r0 = m_base + mt * 16 + g;
            ah[mt][0] = Ah[r0 * SU + kk];
            ah[mt][1] = Ah[(r0 + 8) * SU + kk];
            ah[mt][2] = Ah[r0 * SU + kk + 4];
            ah[mt][3] = Ah[(r0 + 8) * SU + kk + 4];
            al[mt][0] = Al[r0 * SU + kk];
            al[mt][1] = Al[(r0 + 8) * SU + kk];
            al[mt][2] = Al[r0 * SU + kk + 4];
            al[mt][3] = Al[(r0 + 8) * SU + kk + 4];
        }
        const uint4* wrow = Wf + (size_t)(ks * 4 + t) * 128 + cb + g;
#pragma unroll
        for (int nt = 0; nt < 8; nt++) {
            uint4 f = __ldg(wrow + nt * 8);
#pragma unroll
            for (int mt = 0; mt < 2; mt++) {
                MMA_BF16(c[mt][nt], ah[mt][0], ah[mt][1], ah[mt][2], ah[mt][3], f.x, f.y);
                MMA_BF16(c[mt][nt], al[mt][0], al[mt][1], al[mt][2], al[mt][3], f.x, f.y);
                MMA_BF16(c[mt][nt], ah[mt][0], ah[mt][1], ah[mt][2], ah[mt][3], f.z, f.w);
            }
        }
    }

    if (cb == 0) {
        // zl -> packed fp16 message rows (uint32 index i holds dims 2i, 2i+1)
#pragma unroll
        for (int mt = 0; mt < 2; mt++) {
#pragma unroll
            for (int nt = 0; nt < 8; nt++) {
                uint32_t p0 = pack_half2(c[mt][nt][0], c[mt][nt][1]);
                uint32_t p1 = pack_half2(c[mt][nt][2], c[mt][nt][3]);
                size_t r0 = (size_t)(node0 + m_base + mt * 16 + g);
                g_zlb[r0 * 32 + nt * 4 + t]       = p0;
                g_zlb[(r0 + 8) * 32 + nt * 4 + t] = p1;
            }
        }
    } else {
#pragma unroll
        for (int mt = 0; mt < 2; mt++) {
#pragma unroll
            for (int nt = 0; nt < 8; nt++) {
                int colg = nt * 8 + 2 * t;
                size_t r0 = (size_t)(node0 + m_base + mt * 16 + g);
                *(float2*)&G_ZR[r0 * D_EMB + colg]       = make_float2(c[mt][nt][0], c[mt][nt][1]);
                *(float2*)&G_ZR[(r0 + 8) * D_EMB + colg] = make_float2(c[mt][nt][2], c[mt][nt][3]);
            }
        }
    }
}

// ================== fused gather-aggregate + epilogue (fp16 messages) ==========
template <bool FUSE_POOL>
__global__ void gather_h_kernel(const float* __restrict__ b) {
    const int lane = threadIdx.x & 31;
    const int wrp  = threadIdx.x >> 5;
    const int node = blockIdx.x * 8 + wrp;
    const int strm = lane >> 3;          // 0..3
    const int q    = lane & 7;           // uint4 index within the 128B row

    const int beg = g_off[node];
    const int deg = g_deg[node];
    const int end = beg + deg;

    const uint4* zlb = (const uint4*)g_zlb;
    float a[8];
#pragma unroll
    for (int i = 0; i < 8; i++) a[i] = 0.f;

    int j = beg + strm;                  // this stream: j, j+4, j+8, ...
    for (; j + 12 < end; j += 16) {      // 4 edges per stream in flight
        int e0 = g_csr[j], e1 = g_csr[j + 4], e2 = g_csr[j + 8], e3 = g_csr[j + 12];
        uint4 u0 = __ldg(&zlb[(size_t)e0 * 8 + q]);
        uint4 u1 = __ldg(&zlb[(size_t)e1 * 8 + q]);
        uint4 u2 = __ldg(&zlb[(size_t)e2 * 8 + q]);
        uint4 u3 = __ldg(&zlb[(size_t)e3 * 8 + q]);
        acc8(a, u0); acc8(a, u1); acc8(a, u2); acc8(a, u3);
    }
    for (; j < end; j += 4) {
        uint4 u = __ldg(&zlb[(size_t)g_csr[j] * 8 + q]);
        acc8(a, u);
    }

    // combine the 4 streams: lane l += lane l+16, then += lane l+8
#pragma unroll
    for (int i = 0; i < 8; i++) {
        a[i] += __shfl_down_sync(0xffffffffu, a[i], 16);
        a[i] += __shfl_down_sync(0xffffffffu, a[i], 8);
    }

    float4 h0, h1;
    if (strm == 0) {                     // lanes 0-7 hold dims q*8 .. q*8+7
        const float inv = 1.0f / (float)max(deg, 1);
        float4 zr0 = ((const float4*)G_ZR)[(size_t)node * 16 + q * 2];
        float4 zr1 = ((const float4*)G_ZR)[(size_t)node * 16 + q * 2 + 1];
        float4 b0 = __ldg(&((const float4*)b)[q * 2]);
        float4 b1 = __ldg(&((const float4*)b)[q * 2 + 1]);
        h0.x = a[0] * inv + b0.x + zr0.x;
        h0.y = a[1] * inv + b0.y + zr0.y;
        h0.z = a[2] * inv + b0.z + zr0.z;
        h0.w = a[3] * inv + b0.w + zr0.w;
        h1.x = a[4] * inv + b1.x + zr1.x;
        h1.y = a[5] * inv + b1.y + zr1.y;
        h1.z = a[6] * inv + b1.z + zr1.z;
        h1.w = a[7] * inv + b1.w + zr1.w;
        if (!FUSE_POOL) {
            ((float4*)G_H)[(size_t)node * 16 + q * 2]     = h0;
            ((float4*)G_H)[(size_t)node * 16 + q * 2 + 1] = h1;
        }
    }

    if (FUSE_POOL) {
        __shared__ float4 red[8][16];
        if (strm == 0) {
            red[wrp][q * 2]     = h0;
            red[wrp][q * 2 + 1] = h1;
        }
        __syncthreads();
        if (threadIdx.x < 64) {
            const int qq = threadIdx.x >> 2, comp = threadIdx.x & 3;
            float sum = 0.f;
#pragma unroll
            for (int w = 0; w < 8; w++) {
                float4 v = red[w][qq];
                sum += (comp == 0) ? v.x : (comp == 1) ? v.y : (comp == 2) ? v.z : v.w;
            }
            const int g = (blockIdx.x * 8) / NODES_PER_GRAPH;
            atomicAdd(&g_pool[g * D_EMB + qq * 4 + comp], sum);
        }
    }
}

// ================== MLP head =================================================
__global__ void head_kernel(const float* __restrict__ fc1_W,
                            const float* __restrict__ fc1_b,
                            const float* __restrict__ fc2_W,
                            const float* __restrict__ fc2_b,
                            float* __restrict__ out) {
    __shared__ float gs[D_EMB];
    __shared__ float hs[D_HID];
    const int g = blockIdx.x, tid = threadIdx.x;
    if (tid < D_EMB) gs[tid] = g_pool[g * D_EMB + tid] * (1.0f / NODES_PER_GRAPH);
    __syncthreads();
    if (tid < D_HID) {
        float acc = fc1_b[tid];
        const float* w = fc1_W + (size_t)tid * D_EMB;
#pragma unroll
        for (int k = 0; k < D_EMB; k++) acc += gs[k] * w[k];
        hs[tid] = fmaxf(acc, 0.f);
    }
    __syncthreads();
    for (int a = tid; a < N_ACT; a += 256) {
        const float4* w = (const float4*)(fc2_W + (size_t)a * D_HID);
        float a0 = 0.f, a1 = 0.f, a2 = 0.f, a3 = 0.f;
#pragma unroll
        for (int k = 0; k < D_HID / 4; k++) {
            float4 wv = __ldg(&w[k]);
            a0 += wv.x * hs[4 * k + 0];
            a1 += wv.y * hs[4 * k + 1];
            a2 += wv.z * hs[4 * k + 2];
            a3 += wv.w * hs[4 * k + 3];
        }
        out[(size_t)g * N_ACT + a] = fc2_b[a] + (a0 + a1) + (a2 + a3);
    }
}

// ================== launch ===================================================
extern "C" void kernel_launch(void* const* d_in, const int* in_sizes, int n_in,
                              void* d_out, int out_size) {
    const float* x     = (const float*)d_in[0];
    const int*   ei    = (const int*)d_in[1];
    const float* W1l   = (const float*)d_in[2];
    const float* b1l   = (const float*)d_in[3];
    const float* W1r   = (const float*)d_in[4];
    const float* W2l   = (const float*)d_in[5];
    const float* b2l   = (const float*)d_in[6];
    const float* W2r   = (const float*)d_in[7];
    const float* fc1_W = (const float*)d_in[8];
    const float* fc1_b = (const float*)d_in[9];
    const float* fc2_W = (const float*)d_in[10];
    const float* fc2_b = (const float*)d_in[11];
    float* out = (float*)d_out;

    const int* src = ei;
    const int* dst = ei + N_EDGES;

    const int SMEM1 = 2 * 128 * (D_IN / 2 + 4) * 4;   // 69632 B
    const int SMEM2 = 2 * 128 * (D_EMB / 2 + 4) * 4;  // 36864 B
    cudaFuncSetAttribute(lin_tc_kernel<D_IN>,  cudaFuncAttributeMaxDynamicSharedMemorySize, SMEM1);
    cudaFuncSetAttribute(lin_tc_kernel<D_EMB>, cudaFuncAttributeMaxDynamicSharedMemorySize, SMEM2);

    init_kernel<<<N_NODES / 256, 256>>>(W1l, W1r, W2l, W2r);
    hist_kernel<<<2048, 256>>>(dst);
    alloc_kernel<<<N_NODES / 256, 256>>>();
    scatter_kernel<<<2048, 256>>>(src, dst);      // profiler slot #4 (control)

    lin_tc_kernel<D_IN><<<N_NODES / 128, 256, SMEM1>>>(x);
    gather_h_kernel<false><<<N_NODES / 8, 256>>>(b1l);

    lin_tc_kernel<D_EMB><<<N_NODES / 128, 256, SMEM2>>>(nullptr);
    gather_h_kernel<true><<<N_NODES / 8, 256>>>(b2l);

    head_kernel<<<N_GRAPHS, 256>>>(fc1_W, fc1_b, fc2_W, fc2_b, out);
}